// round 16
// baseline (speedup 1.0000x reference)
#include <cuda_runtime.h>
#include <cstdint>

// ---------------------------------------------------------------------------
// B=512, N=256, H=128
//   A2 = A[:,:,:256] + A[:,:,256:],  d_i = rsqrt(rowsum(A2)+1)
//   A_mix = 0.8*D*A2*D + diag(c),    c_i = 0.1 + d_i^2*(0.7 - 0.1*A2_ii)
//   out = A_mix @ (A_mix @ emb[idx])
// Z-space: Z0 = D*emb[idx]; Z1 = 0.8 d^2 (A2@Z0) + c.*Z0;
//          out = 0.8 d (A2@Z1) + (c/d).*Z1
//
// Kernels = R10 (best: prep at LTS roofline; GEMM free-running warps, no
// mainloop barriers, fragment-permuted L2-resident A2, warp tile 64x32).
// NEW: graph-level pipelining. Batches split into 8 chunks of 64. prep(c0)
// on the main stream; prep(c1..c7) on a forked stream; each gemm(cj) waits
// event evP[j]. The captured graph holds independent prep/gemm nodes that
// the HW co-schedules: gemm chunk = 128 CTAs < 296 slots, prep fills the
// rest, prep's HBM traffic hides under gemm's idle DRAM pipe.
// ---------------------------------------------------------------------------

#define Bsz 512
#define Nn  256
#define Hh  128
#define NNODE 50000
#define NCHUNK 8
#define CHUNK (Bsz / NCHUNK)

__device__ float g_A2p[(size_t)Bsz * Nn * Nn];   // fragment-permuted tf32
__device__ float g_d  [(size_t)Bsz * Nn];
__device__ float g_c  [(size_t)Bsz * Nn];

__device__ __forceinline__ float to_tf32(float x) {
    uint32_t u;
    asm("cvt.rna.tf32.f32 %0, %1;" : "=r"(u) : "f"(x));
    return __uint_as_float(u);
}

// ---------------------------------------------------------------------------
// prep: 16-row slab per block. d, c, fragment-permuted tf32 A2 image
// (k8-major). grid (16, CHUNK), block 256. Batch = b0 + blockIdx.y.
// ---------------------------------------------------------------------------
__global__ __launch_bounds__(256)
void prep_kernel(const float* __restrict__ A, int b0) {
    __shared__ float s2[16 * 260];
    const int b    = b0 + blockIdx.y;
    const int mblk = blockIdx.x;
    const int t    = threadIdx.x;
    const int i0   = mblk * 16;

    #pragma unroll
    for (int p = 0; p < 4; p++) {
        int fidx = t + p * 256;
        int row  = fidx >> 6;
        int c4   = fidx & 63;
        const float4* src =
            (const float4*)(A + ((size_t)(b * Nn + i0 + row)) * (2 * Nn));
        float4 a  = src[c4];
        float4 bb = src[c4 + 64];
        *(float4*)(s2 + row * 260 + c4 * 4) =
            make_float4(a.x + bb.x, a.y + bb.y, a.z + bb.z, a.w + bb.w);
    }
    __syncthreads();

    const int lane = t & 31, w = t >> 5;
    #pragma unroll
    for (int rr = 0; rr < 2; rr++) {
        int row = w * 2 + rr;
        float s = 0.0f;
        #pragma unroll
        for (int k = 0; k < 8; k++) s += s2[row * 260 + lane + 32 * k];
        #pragma unroll
        for (int o = 16; o; o >>= 1) s += __shfl_xor_sync(0xFFFFFFFFu, s, o);
        if (lane == 0) {
            int i = i0 + row;
            float aii = s2[row * 260 + i];
            float d = rsqrtf(s + 1.0f);
            g_d[b * Nn + i] = d;
            g_c[b * Nn + i] = 0.1f + d * d * (0.7f - 0.1f * aii);
        }
    }

    // fragment-permuted, k8-major write: dst[k8*512 + mblk*32 + lane]
    float4* dst = (float4*)g_A2p + (size_t)b * 16384;
    #pragma unroll
    for (int p = 0; p < 4; p++) {
        int q    = t + p * 256;
        int k8   = q >> 5;
        int lp   = q & 31;
        int gr2  = lp >> 2, tc2 = lp & 3;
        int col  = k8 * 8;
        float e0 = s2[(gr2    ) * 260 + col + tc2    ];
        float e1 = s2[(gr2 + 8) * 260 + col + tc2    ];
        float e2 = s2[(gr2    ) * 260 + col + tc2 + 4];
        float e3 = s2[(gr2 + 8) * 260 + col + tc2 + 4];
        dst[k8 * 512 + mblk * 32 + lp] =
            make_float4(to_tf32(e0), to_tf32(e1), to_tf32(e2), to_tf32(e3));
    }
}

// ---------------------------------------------------------------------------
__device__ __forceinline__ void mma_tf32(float* c, const uint32_t* a, const uint32_t* b) {
    asm volatile(
        "mma.sync.aligned.m16n8k8.row.col.f32.tf32.tf32.f32 "
        "{%0,%1,%2,%3}, {%4,%5,%6,%7}, {%8,%9}, {%0,%1,%2,%3};\n"
        : "+f"(c[0]), "+f"(c[1]), "+f"(c[2]), "+f"(c[3])
        : "r"(a[0]), "r"(a[1]), "r"(a[2]), "r"(a[3]),
          "r"(b[0]), "r"(b[1]));
}

// ---------------------------------------------------------------------------
// Fused GEMM (verbatim R10). grid (2 h-halves, CHUNK), block 256
// (8 warps: 4m x 2n, warp tile 64x32). smem 71.7KB -> 2 CTAs/SM.
// ---------------------------------------------------------------------------
#define ZP_STRIDE 68                     // pair-units per tc-row (mod 16 == 4)
#define SZ_FLOATS (128 * ZP_STRIDE * 2)  // 17408 floats
#define SMEM_FLOATS (SZ_FLOATS + 2 * 256)

__global__ __launch_bounds__(256, 2)
void sgc_fused(const void* __restrict__ idx_raw,
               const float* __restrict__ emb,
               float* __restrict__ out,
               int b0) {
    extern __shared__ float smem[];
    float* sZ = smem;
    float* sd = smem + SZ_FLOATS;
    float* sc = sd + 256;

    const int half = blockIdx.x;
    const int b    = b0 + blockIdx.y;
    const int tid  = threadIdx.x;
    const int lane = tid & 31;
    const int w    = tid >> 5;
    const int wm   = w & 3;
    const int wn   = w >> 2;
    const int gr   = lane >> 2;
    const int tc   = lane & 3;

    // index dtype detection (true int64 indices < 50000 -> high words zero)
    const unsigned long long* iq = (const unsigned long long*)idx_raw;
    int is64 = 1;
    #pragma unroll
    for (int i = 0; i < 16; i++)
        if (iq[i] >> 32) is64 = 0;

    sd[tid] = g_d[b * Nn + tid];
    sc[tid] = g_c[b * Nn + tid];
    __syncthreads();

    // Z0 gather: thread <-> k row; this half's 64 emb columns
    {
        const int k = tid;
        long long node = is64 ? ((const long long*)idx_raw)[b * Nn + k]
                              : (long long)((const int*)idx_raw)[b * Nn + k];
        if (node < 0) node = 0;
        if (node >= NNODE) node = NNODE - 1;
        const float dk = sd[k];
        const int slot = (k >> 3) * 4 + (k & 3);
        const int comp = (k >> 2) & 1;
        float* zrow = sZ + slot * (ZP_STRIDE * 2) + comp;
        const float4* src = (const float4*)(emb + (size_t)node * Hh + half * 64);
        #pragma unroll
        for (int j = 0; j < 16; j++) {
            float4 v = src[j];
            const int h = j * 4;
            zrow[(h    ) * 2] = to_tf32(dk * v.x);
            zrow[(h + 1) * 2] = to_tf32(dk * v.y);
            zrow[(h + 2) * 2] = to_tf32(dk * v.z);
            zrow[(h + 3) * 2] = to_tf32(dk * v.w);
        }
    }
    __syncthreads();

    const float4* __restrict__ A2f4 =
        (const float4*)g_A2p + (size_t)b * 16384 + (wm * 4) * 32 + lane;

    float acc[4][4][4];
    auto zero_acc = [&]() {
        #pragma unroll
        for (int mt = 0; mt < 4; mt++)
            #pragma unroll
            for (int nt = 0; nt < 4; nt++)
                #pragma unroll
                for (int e = 0; e < 4; e++) acc[mt][nt][e] = 0.0f;
    };

    // free-running mainloop: NO barriers; 1-k8-ahead A register prefetch
    auto run_round = [&]() {
        float4 abuf[2][4];
        #pragma unroll
        for (int mt = 0; mt < 4; mt++)
            abuf[0][mt] = __ldg(A2f4 + mt * 32);

        #pragma unroll 2
        for (int k8 = 0; k8 < 32; k8++) {
            const int cur = k8 & 1;
            if (k8 < 31) {
                const float4* nsrc = A2f4 + (k8 + 1) * 512;
                #pragma unroll
                for (int mt = 0; mt < 4; mt++)
                    abuf[cur ^ 1][mt] = __ldg(nsrc + mt * 32);
            }
            uint32_t bf[4][2];
            #pragma unroll
            for (int nt = 0; nt < 4; nt++) {
                const int cb = wn * 32 + nt * 8 + gr;
                float2 bv = *(const float2*)(sZ +
                            ((k8 * 4 + tc) * ZP_STRIDE + cb) * 2);
                bf[nt][0] = __float_as_uint(bv.x);
                bf[nt][1] = __float_as_uint(bv.y);
            }
            #pragma unroll
            for (int mt = 0; mt < 4; mt++) {
                uint32_t af[4];
                af[0] = __float_as_uint(abuf[cur][mt].x);
                af[1] = __float_as_uint(abuf[cur][mt].y);
                af[2] = __float_as_uint(abuf[cur][mt].z);
                af[3] = __float_as_uint(abuf[cur][mt].w);
                #pragma unroll
                for (int nt = 0; nt < 4; nt++)
                    mma_tf32(acc[mt][nt], af, bf[nt]);
            }
        }
    };

    // ================= round 0 =================
    zero_acc();
    run_round();

    __syncthreads();   // all warps done READING sZ before it is rewritten

    // epilogue 0: Z1 = tf32(0.8 d^2 W0 + c Z0), in place
    #pragma unroll
    for (int mt = 0; mt < 4; mt++) {
        #pragma unroll
        for (int rr = 0; rr < 2; rr++) {
            const int r = wm * 64 + mt * 16 + gr + rr * 8;
            const float ws = 0.8f * sd[r] * sd[r];
            const float cc = sc[r];
            float* base = sZ + ((r >> 3) * 4 + (r & 3)) * (ZP_STRIDE * 2)
                             + ((r >> 2) & 1);
            #pragma unroll
            for (int nt = 0; nt < 4; nt++) {
                const int col = wn * 32 + nt * 8 + tc * 2;
                float z0 = base[(col    ) * 2];
                float z1 = base[(col + 1) * 2];
                base[(col    ) * 2] = to_tf32(ws * acc[mt][nt][rr * 2 + 0] + cc * z0);
                base[(col + 1) * 2] = to_tf32(ws * acc[mt][nt][rr * 2 + 1] + cc * z1);
            }
        }
    }
    __syncthreads();

    // ================= round 1 =================
    zero_acc();
    run_round();

    // epilogue 1: out = 0.8 d W1 + (c/d) Z1   (sZ read-only here)
    float* __restrict__ dstb = out + (size_t)b * Nn * Hh + half * 64;
    #pragma unroll
    for (int mt = 0; mt < 4; mt++) {
        #pragma unroll
        for (int rr = 0; rr < 2; rr++) {
            const int r = wm * 64 + mt * 16 + gr + rr * 8;
            const float dk = sd[r];
            const float ws = 0.8f * dk;
            const float zs = sc[r] / dk;
            const float* base = sZ + ((r >> 3) * 4 + (r & 3)) * (ZP_STRIDE * 2)
                                   + ((r >> 2) & 1);
            #pragma unroll
            for (int nt = 0; nt < 4; nt++) {
                const int col = wn * 32 + nt * 8 + tc * 2;
                float o0 = ws * acc[mt][nt][rr * 2 + 0] + zs * base[(col    ) * 2];
                float o1 = ws * acc[mt][nt][rr * 2 + 1] + zs * base[(col + 1) * 2];
                *(float2*)(dstb + (size_t)r * Hh + col) = make_float2(o0, o1);
            }
        }
    }
}

// ---------------------------------------------------------------------------
// Launch: graph-level pipeline. prep(c0) on main stream; prep(c1..7) on a
// forked stream (joined via events); gemm(cj) gated on evP[j]. The captured
// graph co-schedules prep(c_{j+1..}) with gemm(c_j).
// ---------------------------------------------------------------------------
extern "C" void kernel_launch(void* const* d_in, const int* in_sizes, int n_in,
                              void* d_out, int out_size) {
    const void*  inputs = nullptr;
    const float* A      = nullptr;
    const float* emb    = nullptr;

    for (int i = 0; i < n_in; ++i) {
        if (in_sizes[i] == Bsz * Nn)               inputs = d_in[i];
        else if (in_sizes[i] == Bsz * Nn * 2 * Nn) A      = (const float*)d_in[i];
        else if (in_sizes[i] == NNODE * Hh)        emb    = (const float*)d_in[i];
    }
    if (!inputs) inputs = d_in[0];
    if (!A)      A      = (const float*)d_in[1];
    if (!emb)    emb    = (const float*)d_in[2];

    float* out = (float*)d_out;

    static cudaStream_t s2 = nullptr;
    static cudaEvent_t  evP[NCHUNK];
    const int smem_bytes = SMEM_FLOATS * sizeof(float);   // 71,680 B
    if (!s2) {
        cudaFuncSetAttribute(sgc_fused,
                             cudaFuncAttributeMaxDynamicSharedMemorySize,
                             smem_bytes);
        cudaStreamCreateWithFlags(&s2, cudaStreamNonBlocking);
        for (int j = 0; j < NCHUNK; j++)
            cudaEventCreateWithFlags(&evP[j], cudaEventDisableTiming);
    }

    // chunk 0 prep on the main (capturing) stream
    prep_kernel<<<dim3(16, CHUNK), 256, 0, 0>>>(A, 0);
    cudaEventRecord(evP[0], 0);

    // fork: remaining prep chunks on s2
    cudaStreamWaitEvent(s2, evP[0], 0);
    for (int j = 1; j < NCHUNK; j++) {
        prep_kernel<<<dim3(16, CHUNK), 256, 0, s2>>>(A, j * CHUNK);
        cudaEventRecord(evP[j], s2);
    }

    // gemm chunks on the main stream, each gated on its prep chunk
    sgc_fused<<<dim3(2, CHUNK), 256, smem_bytes, 0>>>(inputs, emb, out, 0);
    for (int j = 1; j < NCHUNK; j++) {
        cudaStreamWaitEvent(0, evP[j], 0);
        sgc_fused<<<dim3(2, CHUNK), 256, smem_bytes, 0>>>(inputs, emb, out,
                                                          j * CHUNK);
    }
}

// round 17
// speedup vs baseline: 1.9045x; 1.9045x over previous
#include <cuda_runtime.h>
#include <cuda_fp16.h>
#include <cstdint>

// ---------------------------------------------------------------------------
// B=512, N=256, H=128
//   A2 = A[:,:,:256] + A[:,:,256:],  d_i = rsqrt(rowsum(A2)+1)
//   A_mix = 0.8*D*A2*D + diag(c),    c_i = 0.1 + d_i^2*(0.7 - 0.1*A2_ii)
//   out = A_mix @ (A_mix @ emb[idx])
// Z-space: Z0 = D*emb[idx]; Z1 = 0.8 d^2 (A2@Z0) + c.*Z0;
//          out = 0.8 d (A2@Z1) + (c/d).*Z1
//
// Engine: fp16 HMMA m16n8k16 (2x tf32 rate; fp16 sig = 11 bits = tf32 ->
// same precision; fp32 accumulators). Structure = R10: free-running warps,
// no mainloop barriers, fragment-permuted A in gmem (L2-resident, now fp16 =
// 64MB image), 1-k16-ahead register prefetch, warp tile 64x32.
//   A2p per batch: [k16 16][mblk 16][lane 32] uint4
//     lane(gr,tc): a0=(A[gr][2tc],A[gr][2tc+1]) a1=(A[gr+8][..]) rows +mblk*16
//                  a2=(A[gr][2tc+8],+9)         a3=(A[gr+8][..]), cols +k16*16
//   Z in smem as uint2 words: word(s = k16*4+tc, col) = {b0=(Z[k16*16+2tc],
//     Z[..+1]), b1=(Z[k16*16+8+2tc], Z[..+9])} -> B frag = ONE LDS.64
// ---------------------------------------------------------------------------

#define Bsz 512
#define Nn  256
#define Hh  128
#define NNODE 50000

__device__ uint4 g_A2p[(size_t)Bsz * 8192];      // fp16 fragment images, 64MB
__device__ float g_d  [(size_t)Bsz * Nn];
__device__ float g_c  [(size_t)Bsz * Nn];

__device__ __forceinline__ uint32_t h2pack(float a, float b) {
    __half2 h = __floats2half2_rn(a, b);
    return *(uint32_t*)&h;
}

// half-index of Z[k][h] inside the packed smem Z image
__device__ __forceinline__ int zhidx(int k, int h) {
    return (((((k >> 4) * 4) + ((k >> 1) & 3)) * 68 + h) << 2)
           + (((k >> 3) & 1) << 1) + (k & 1);
}

// ---------------------------------------------------------------------------
// prep: 16-row slab per block. d, c, fp16 fragment-permuted A2 image.
// grid (16, 512), block 256.
// ---------------------------------------------------------------------------
__global__ __launch_bounds__(256)
void prep_kernel(const float* __restrict__ A) {
    __shared__ float s2[16 * 260];
    const int b    = blockIdx.y;
    const int mblk = blockIdx.x;
    const int t    = threadIdx.x;
    const int i0   = mblk * 16;

    #pragma unroll
    for (int p = 0; p < 4; p++) {
        int fidx = t + p * 256;
        int row  = fidx >> 6;
        int c4   = fidx & 63;
        const float4* src =
            (const float4*)(A + ((size_t)(b * Nn + i0 + row)) * (2 * Nn));
        float4 a  = src[c4];
        float4 bb = src[c4 + 64];
        *(float4*)(s2 + row * 260 + c4 * 4) =
            make_float4(a.x + bb.x, a.y + bb.y, a.z + bb.z, a.w + bb.w);
    }
    __syncthreads();

    const int lane = t & 31, w = t >> 5;
    #pragma unroll
    for (int rr = 0; rr < 2; rr++) {
        int row = w * 2 + rr;
        float s = 0.0f;
        #pragma unroll
        for (int k = 0; k < 8; k++) s += s2[row * 260 + lane + 32 * k];
        #pragma unroll
        for (int o = 16; o; o >>= 1) s += __shfl_xor_sync(0xFFFFFFFFu, s, o);
        if (lane == 0) {
            int i = i0 + row;
            float aii = s2[row * 260 + i];
            float d = rsqrtf(s + 1.0f);
            g_d[b * Nn + i] = d;
            g_c[b * Nn + i] = 0.1f + d * d * (0.7f - 0.1f * aii);
        }
    }

    // fp16 fragment write: 512 uint4 per mblk (16 k16 x 32 lanes)
    uint4* dst = g_A2p + (size_t)b * 8192;
    #pragma unroll
    for (int p = 0; p < 2; p++) {
        int q    = t + p * 256;          // 0..511 = k16*32 + lp
        int k16  = q >> 5;
        int lp   = q & 31;
        int gr2  = lp >> 2, tc2 = lp & 3;
        int c0   = k16 * 16 + tc2 * 2;
        const float* r0 = s2 + gr2 * 260;
        const float* r1 = s2 + (gr2 + 8) * 260;
        uint4 v;
        v.x = h2pack(r0[c0],     r0[c0 + 1]);   // a0
        v.y = h2pack(r1[c0],     r1[c0 + 1]);   // a1
        v.z = h2pack(r0[c0 + 8], r0[c0 + 9]);   // a2
        v.w = h2pack(r1[c0 + 8], r1[c0 + 9]);   // a3
        dst[k16 * 512 + mblk * 32 + lp] = v;
    }
}

// ---------------------------------------------------------------------------
__device__ __forceinline__ void mma_f16(float* c, const uint4 a,
                                        uint32_t b0, uint32_t b1) {
    asm volatile(
        "mma.sync.aligned.m16n8k16.row.col.f32.f16.f16.f32 "
        "{%0,%1,%2,%3}, {%4,%5,%6,%7}, {%8,%9}, {%0,%1,%2,%3};\n"
        : "+f"(c[0]), "+f"(c[1]), "+f"(c[2]), "+f"(c[3])
        : "r"(a.x), "r"(a.y), "r"(a.z), "r"(a.w), "r"(b0), "r"(b1));
}

// ---------------------------------------------------------------------------
// Fused GEMM. grid (2 h-halves, 512 batches), block 256 (8 warps: 4m x 2n,
// warp tile 64x32). smem: Z 34.8KB + d/c 2KB -> 2 CTAs/SM (regfile-bound).
// ---------------------------------------------------------------------------
#define ZW_STRIDE 68                       // uint2 words per slot row
#define SZ_U2     (64 * ZW_STRIDE)         // 4352 uint2 = 34816 B
#define SMEM_BYTES (SZ_U2 * 8 + 2 * 256 * 4)

__global__ __launch_bounds__(256, 2)
void sgc_fused(const void* __restrict__ idx_raw,
               const float* __restrict__ emb,
               float* __restrict__ out) {
    extern __shared__ float smem[];
    uint2*  sZ  = (uint2*)smem;
    __half* sZh = (__half*)smem;
    float*  sd  = smem + SZ_U2 * 2;
    float*  sc  = sd + 256;

    const int half = blockIdx.x;
    const int b    = blockIdx.y;
    const int tid  = threadIdx.x;
    const int lane = tid & 31;
    const int w    = tid >> 5;
    const int wm   = w & 3;
    const int wn   = w >> 2;
    const int gr   = lane >> 2;
    const int tc   = lane & 3;

    // index dtype detection (true int64 indices < 50000 -> high words zero)
    const unsigned long long* iq = (const unsigned long long*)idx_raw;
    int is64 = 1;
    #pragma unroll
    for (int i = 0; i < 16; i++)
        if (iq[i] >> 32) is64 = 0;

    sd[tid] = g_d[b * Nn + tid];
    sc[tid] = g_c[b * Nn + tid];
    __syncthreads();

    // Z0 gather: thread <-> k row; this half's 64 emb columns (fp16 rn)
    {
        const int k = tid;
        long long node = is64 ? ((const long long*)idx_raw)[b * Nn + k]
                              : (long long)((const int*)idx_raw)[b * Nn + k];
        if (node < 0) node = 0;
        if (node >= NNODE) node = NNODE - 1;
        const float dk = sd[k];
        __half* zp = sZh + zhidx(k, 0);       // +4 halves per h step
        const float4* src = (const float4*)(emb + (size_t)node * Hh + half * 64);
        #pragma unroll
        for (int j = 0; j < 16; j++) {
            float4 v = src[j];
            const int h = j * 4;
            zp[(h    ) * 4] = __float2half_rn(dk * v.x);
            zp[(h + 1) * 4] = __float2half_rn(dk * v.y);
            zp[(h + 2) * 4] = __float2half_rn(dk * v.z);
            zp[(h + 3) * 4] = __float2half_rn(dk * v.w);
        }
    }
    __syncthreads();

    const uint4* __restrict__ A2f =
        g_A2p + (size_t)b * 8192 + (wm * 4) * 32 + lane;

    float acc[4][4][4];
    auto zero_acc = [&]() {
        #pragma unroll
        for (int mt = 0; mt < 4; mt++)
            #pragma unroll
            for (int nt = 0; nt < 4; nt++)
                #pragma unroll
                for (int e = 0; e < 4; e++) acc[mt][nt][e] = 0.0f;
    };

    // free-running mainloop: NO barriers; 1-k16-ahead A register prefetch
    auto run_round = [&]() {
        uint4 abuf[2][4];
        #pragma unroll
        for (int mt = 0; mt < 4; mt++)
            abuf[0][mt] = __ldg(A2f + mt * 32);

        #pragma unroll 2
        for (int k16 = 0; k16 < 16; k16++) {
            const int cur = k16 & 1;
            if (k16 < 15) {
                const uint4* nsrc = A2f + (k16 + 1) * 512;
                #pragma unroll
                for (int mt = 0; mt < 4; mt++)
                    abuf[cur ^ 1][mt] = __ldg(nsrc + mt * 32);
            }
            uint2 bf[4];
            #pragma unroll
            for (int nt = 0; nt < 4; nt++)
                bf[nt] = sZ[(k16 * 4 + tc) * ZW_STRIDE + wn * 32 + nt * 8 + gr];
            #pragma unroll
            for (int mt = 0; mt < 4; mt++)
                #pragma unroll
                for (int nt = 0; nt < 4; nt++)
                    mma_f16(acc[mt][nt], abuf[cur][mt], bf[nt].x, bf[nt].y);
        }
    };

    // ================= round 0 =================
    zero_acc();
    run_round();

    __syncthreads();   // all warps done READING sZ before it is rewritten

    // epilogue 0: Z1 = fp16(0.8 d^2 W0 + c Z0), in place
    #pragma unroll
    for (int mt = 0; mt < 4; mt++) {
        #pragma unroll
        for (int rr = 0; rr < 2; rr++) {
            const int r = wm * 64 + mt * 16 + gr + rr * 8;
            const float ws = 0.8f * sd[r] * sd[r];
            const float cc = sc[r];
            #pragma unroll
            for (int nt = 0; nt < 4; nt++) {
                const int col = wn * 32 + nt * 8 + tc * 2;
                __half* p0 = sZh + zhidx(r, col);
                __half* p1 = p0 + 4;
                float z0 = __half2float(*p0);
                float z1 = __half2float(*p1);
                *p0 = __float2half_rn(ws * acc[mt][nt][rr * 2 + 0] + cc * z0);
                *p1 = __float2half_rn(ws * acc[mt][nt][rr * 2 + 1] + cc * z1);
            }
        }
    }
    __syncthreads();

    // ================= round 1 =================
    zero_acc();
    run_round();

    // epilogue 1: out = 0.8 d W1 + (c/d) Z1   (sZ read-only here)
    float* __restrict__ dstb = out + (size_t)b * Nn * Hh + half * 64;
    #pragma unroll
    for (int mt = 0; mt < 4; mt++) {
        #pragma unroll
        for (int rr = 0; rr < 2; rr++) {
            const int r = wm * 64 + mt * 16 + gr + rr * 8;
            const float dk = sd[r];
            const float ws = 0.8f * dk;
            const float zs = sc[r] / dk;
            #pragma unroll
            for (int nt = 0; nt < 4; nt++) {
                const int col = wn * 32 + nt * 8 + tc * 2;
                const __half* p0 = sZh + zhidx(r, col);
                float o0 = ws * acc[mt][nt][rr * 2 + 0]
                         + zs * __half2float(p0[0]);
                float o1 = ws * acc[mt][nt][rr * 2 + 1]
                         + zs * __half2float(p0[4]);
                *(float2*)(dstb + (size_t)r * Hh + col) = make_float2(o0, o1);
            }
        }
    }
}

// ---------------------------------------------------------------------------
extern "C" void kernel_launch(void* const* d_in, const int* in_sizes, int n_in,
                              void* d_out, int out_size) {
    const void*  inputs = nullptr;
    const float* A      = nullptr;
    const float* emb    = nullptr;

    for (int i = 0; i < n_in; ++i) {
        if (in_sizes[i] == Bsz * Nn)               inputs = d_in[i];
        else if (in_sizes[i] == Bsz * Nn * 2 * Nn) A      = (const float*)d_in[i];
        else if (in_sizes[i] == NNODE * Hh)        emb    = (const float*)d_in[i];
    }
    if (!inputs) inputs = d_in[0];
    if (!A)      A      = (const float*)d_in[1];
    if (!emb)    emb    = (const float*)d_in[2];

    float* out = (float*)d_out;

    static bool attr_set = false;
    if (!attr_set) {
        cudaFuncSetAttribute(sgc_fused,
                             cudaFuncAttributeMaxDynamicSharedMemorySize,
                             SMEM_BYTES);
        attr_set = true;
    }

    prep_kernel<<<dim3(16, Bsz), 256>>>(A);
    sgc_fused<<<dim3(2, Bsz), 256, SMEM_BYTES>>>(inputs, emb, out);
}